// round 15
// baseline (speedup 1.0000x reference)
#include <cuda_runtime.h>
#include <math.h>

#define BB 16
#define TT 1024
#define NN 512
#define DD 512
#define INDIM 1536
#define EPSF 1e-8f

// ---------------- device scratch (no allocations allowed) ----------------
__device__ float g_xt  [BB*NN*TT];
__device__ float g_rc  [BB*NN*TT];
__device__ float g_mu  [BB*NN];
__device__ float g_covP[BB*NN*NN];
__device__ float g_covS[BB*NN*NN];
__device__ float g_P   [BB*NN*NN];
__device__ float g_S   [BB*NN*NN];
__device__ float g_prec[BB*NN*NN];
__device__ float g_C   [BB*NN*NN];
__device__ float g_Af  [BB*NN*NN];
__device__ float g_Ybuf[BB*NN*DD];
__device__ float g_Hbuf[BB*NN*DD];
__device__ float g_stage[BB*NN*NN];
__device__ float g_binv[BB*64*64];
__device__ int   g_flags[BB*8];
__device__ float g_sdP [BB*NN];
__device__ float g_sdS [BB*NN];
__device__ float g_sdQ [BB*NN];
__device__ float g_parts[BB*32*6];
__device__ float g_alph[BB*4];
__device__ float g_dinv[BB*NN];
__device__ float g_lnmu[BB*NN];
__device__ float g_lninv[BB*NN];
__device__ float g_W0g [INDIM*DD];
__device__ float g_vw  [2*DD];
__device__ float g_vwp [96*2*DD];

__constant__ int c_BI[10] = {0,1,1,2,2,2,3,3,3,3};
__constant__ int c_BJ[10] = {0,0,1,0,1,2,0,1,2,3};

// ---------------- tf32 mma helpers ----------------
__device__ __forceinline__ unsigned su32(const void* p) {
    return (unsigned)__cvta_generic_to_shared(p);
}
__device__ __forceinline__ void cpa16(unsigned dst, const void* src) {
    asm volatile("cp.async.cg.shared.global [%0], [%1], 16;" :: "r"(dst), "l"(src));
}
__device__ __forceinline__ void cpcommit() { asm volatile("cp.async.commit_group;"); }
template<int N> __device__ __forceinline__ void cpwait() {
    asm volatile("cp.async.wait_group %0;" :: "n"(N) : "memory");
}
__device__ __forceinline__ void mma_tf32(float* c,
        unsigned a0, unsigned a1, unsigned a2, unsigned a3,
        unsigned b0, unsigned b1) {
    asm volatile("mma.sync.aligned.m16n8k8.row.col.f32.tf32.tf32.f32 "
        "{%0,%1,%2,%3}, {%4,%5,%6,%7}, {%8,%9}, {%0,%1,%2,%3};"
        : "+f"(c[0]), "+f"(c[1]), "+f"(c[2]), "+f"(c[3])
        : "r"(a0), "r"(a1), "r"(a2), "r"(a3), "r"(b0), "r"(b1));
}
__device__ __forceinline__ unsigned f2tf(float f) {
    unsigned r; asm("cvt.rna.tf32.f32 %0, %1;" : "=r"(r) : "f"(f)); return r;
}
__device__ __forceinline__ void tfsplit(float f, unsigned& hi, unsigned& lo) {
    hi = f2tf(f);
    lo = f2tf(f - __uint_as_float(hi));
}

#define ASTR 36
#define BSTR2 264   // 256 + 8 pad, conflict-free B frags for the wide tile
#define ILG  68     // k_inv smem stride (== 4 mod 32, A/B-frag conflict-free)

// ---------------- transpose ----------------
__global__ void k_transpose(const float* __restrict__ x, float* __restrict__ xt) {
    __shared__ float tile[32][33];
    int b = blockIdx.z;
    int n0 = blockIdx.x * 32, t0 = blockIdx.y * 32;
    for (int r = threadIdx.y; r < 32; r += 8)
        tile[r][threadIdx.x] = x[((size_t)b*TT + t0 + r)*NN + n0 + threadIdx.x];
    __syncthreads();
    for (int r = threadIdx.y; r < 32; r += 8)
        xt[((size_t)b*NN + n0 + r)*TT + t0 + threadIdx.x] = tile[threadIdx.x][r];
}

// ---------------- bitonic argsort -> centered ranks (+ mean) --------------
__global__ __launch_bounds__(512) void k_sort(const float* __restrict__ xt,
                                              float* __restrict__ rc,
                                              float* __restrict__ mu) {
    __shared__ unsigned long long keys[1024];
    __shared__ float red[512];
    int bn = blockIdx.x;
    const float* row = xt + (size_t)bn*TT;
    float s = 0.f;
    for (int t = threadIdx.x; t < 1024; t += 512) {
        float v = row[t];
        s += v;
        unsigned u = __float_as_uint(v);
        u = (u & 0x80000000u) ? ~u : (u | 0x80000000u);
        keys[t] = ((unsigned long long)u << 32) | (unsigned)t;
    }
    red[threadIdx.x] = s; __syncthreads();
    for (int o = 256; o > 0; o >>= 1) {
        if (threadIdx.x < o) red[threadIdx.x] += red[threadIdx.x + o];
        __syncthreads();
    }
    if (threadIdx.x == 0) mu[bn] = red[0] * (1.f / TT);
    for (int k2 = 2; k2 <= 1024; k2 <<= 1)
        for (int j = k2 >> 1; j > 0; j >>= 1) {
            int t = threadIdx.x;
            int i = ((t & ~(j-1)) << 1) | (t & (j-1));
            int l = i | j;
            unsigned long long a = keys[i], b2 = keys[l];
            if ((a > b2) == ((i & k2) == 0)) { keys[i] = b2; keys[l] = a; }
            __syncthreads();
        }
    float* out = rc + (size_t)bn*TT;
    for (int p = threadIdx.x; p < 1024; p += 512) {
        int idx = (int)(keys[p] & 0xffffffffu);
        out[idx] = (float)(p+1) - 512.5f;
    }
}

// ---------------- W0g = ln_g ⊙row W0 ----------------
__global__ void k_prepw0(const float* __restrict__ W0, const float* __restrict__ lng,
                         float* __restrict__ W0g) {
    for (int e = blockIdx.x*blockDim.x + threadIdx.x; e < INDIM*DD; e += gridDim.x*blockDim.x)
        W0g[e] = lng[e >> 9] * W0[e];
}

// ---------------- v,w partials (96 blocks of 16 rows) ----------------
__global__ __launch_bounds__(512) void k_prepvw(const float* __restrict__ W0,
        const float* __restrict__ lng, const float* __restrict__ lnb,
        float* __restrict__ vwp) {
    int j = threadIdx.x, bz = blockIdx.x;
    float v = 0.f, w = 0.f;
#pragma unroll
    for (int q = 0; q < 16; ++q) {
        int c = bz*16 + q;
        float wv = W0[(size_t)c*DD + j];
        v += lng[c]*wv; w += lnb[c]*wv;
    }
    vwp[(bz*2+0)*DD + j] = v;
    vwp[(bz*2+1)*DD + j] = w;
}
__global__ __launch_bounds__(512) void k_vwred(const float* __restrict__ vwp,
        const float* __restrict__ b0, float* __restrict__ vw) {
    int j = threadIdx.x;
    float v = 0.f, w = 0.f;
    for (int bz = 0; bz < 96; ++bz) {
        v += vwp[(bz*2+0)*DD + j];
        w += vwp[(bz*2+1)*DD + j];
    }
    vw[j] = v; vw[DD + j] = w + b0[j];
}

// ---------------- tf32 Gram ----------------
__global__ __launch_bounds__(256,2) void k_gram_t(const float* __restrict__ xt,
        const float* __restrict__ rc, const float* __restrict__ mu,
        float* __restrict__ covP, float* __restrict__ covS, float scale) {
    extern __shared__ float sm[];
    float* AS = sm;
    float* BS = sm + 3*128*ASTR;
    int p = blockIdx.x, b = blockIdx.y, z = blockIdx.z;
    int bi = c_BI[p], bj = c_BJ[p];
    int tid = threadIdx.x;
    int lane = tid & 31, w = tid >> 5;
    int gid = lane >> 2, tg = lane & 3;
    int wm = w & 1, wn = w >> 1;
    int m0w = wm*64, n0w = wn*32;
    const float* src = (z ? rc : xt) + (size_t)b*NN*TT;
    const float* Ab = src + (size_t)(bi*128)*TT;
    const float* Bb = src + (size_t)(bj*128)*TT;
    int ar = tid >> 1, ak = (tid & 1)*16;

    auto loads = [&](int s, int kt) {
        const float* ga = Ab + (size_t)ar*TT + kt + ak;
        unsigned da = su32(AS + s*128*ASTR + ar*ASTR + ak);
        const float* gb = Bb + (size_t)ar*TT + kt + ak;
        unsigned db = su32(BS + s*128*ASTR + ar*ASTR + ak);
#pragma unroll
        for (int i = 0; i < 4; ++i) { cpa16(da + 16*i, ga + 4*i); cpa16(db + 16*i, gb + 4*i); }
        cpcommit();
    };

    float c[4][4][4];
#pragma unroll
    for (int i = 0; i < 4; ++i)
#pragma unroll
        for (int j = 0; j < 4; ++j)
#pragma unroll
            for (int q = 0; q < 4; ++q) c[i][j][q] = 0.f;

    const int NT = TT/32;
    loads(0, 0); loads(1, 32);
    for (int it = 0; it < NT; ++it) {
        if (it < NT-1) cpwait<1>(); else cpwait<0>();
        __syncthreads();
        if (it + 2 < NT) loads((it+2)%3, (it+2)*32);
        const float* Asb = AS + (it%3)*128*ASTR;
        const float* Bsb = BS + (it%3)*128*ASTR;
#pragma unroll
        for (int ks = 0; ks < 4; ++ks) {
            int k0 = ks*8;
            unsigned af[4][4], bf[4][2];
#pragma unroll
            for (int mt = 0; mt < 4; ++mt) {
                int m = m0w + mt*16 + gid;
                af[mt][0] = __float_as_uint(Asb[(m  )*ASTR + k0 + tg]);
                af[mt][1] = __float_as_uint(Asb[(m+8)*ASTR + k0 + tg]);
                af[mt][2] = __float_as_uint(Asb[(m  )*ASTR + k0 + tg + 4]);
                af[mt][3] = __float_as_uint(Asb[(m+8)*ASTR + k0 + tg + 4]);
            }
#pragma unroll
            for (int nt = 0; nt < 4; ++nt) {
                int n = n0w + nt*8 + gid;
                bf[nt][0] = __float_as_uint(Bsb[n*ASTR + k0 + tg]);
                bf[nt][1] = __float_as_uint(Bsb[n*ASTR + k0 + tg + 4]);
            }
#pragma unroll
            for (int mt = 0; mt < 4; ++mt)
#pragma unroll
                for (int nt = 0; nt < 4; ++nt)
                    mma_tf32(c[mt][nt], af[mt][0], af[mt][1], af[mt][2], af[mt][3],
                             bf[nt][0], bf[nt][1]);
        }
    }
    float* Cb = (z ? covS : covP) + (size_t)b*NN*NN;
    const float* mub = mu + b*NN;
#pragma unroll
    for (int mt = 0; mt < 4; ++mt) {
#pragma unroll
        for (int nt = 0; nt < 4; ++nt) {
            int r0 = m0w + mt*16 + gid;
            int cb = n0w + nt*8 + tg*2;
            int gi0 = bi*128 + r0, gi1 = gi0 + 8;
            int gj0 = bj*128 + cb, gj1 = gj0 + 1;
            float v00 = c[mt][nt][0], v01 = c[mt][nt][1];
            float v10 = c[mt][nt][2], v11 = c[mt][nt][3];
            if (z == 0) {
                float mi0 = mub[gi0], mi1 = mub[gi1];
                float mj0 = mub[gj0], mj1 = mub[gj1];
                v00 -= 1024.f*mi0*mj0; v01 -= 1024.f*mi0*mj1;
                v10 -= 1024.f*mi1*mj0; v11 -= 1024.f*mi1*mj1;
            }
            v00 *= scale; v01 *= scale; v10 *= scale; v11 *= scale;
            *(float2*)&Cb[(size_t)gi0*NN + gj0] = make_float2(v00, v01);
            *(float2*)&Cb[(size_t)gi1*NN + gj0] = make_float2(v10, v11);
            if (bi != bj) {
                Cb[(size_t)gj0*NN + gi0] = v00;
                Cb[(size_t)gj1*NN + gi0] = v01;
                Cb[(size_t)gj0*NN + gi1] = v10;
                Cb[(size_t)gj1*NN + gi1] = v11;
            }
        }
    }
}

// ------- wide-tile tf32 GEMM: CTA 128x256, warp 64x64, 1 CTA/SM -----------
__global__ __launch_bounds__(256,1) void k_mm_w(const float* __restrict__ A, long long sA,
        const float* __restrict__ Bm, long long sB, const float* __restrict__ bias,
        const float* __restrict__ rs,
        float* __restrict__ Cm, long long sC, int K, int relu) {
    extern __shared__ float sm[];
    float* AS = sm;
    float* BS = sm + 3*128*ASTR;
    int bj = blockIdx.x, bi = blockIdx.y, b = blockIdx.z;
    int tid = threadIdx.x;
    int lane = tid & 31, w = tid >> 5;
    int gid = lane >> 2, tg = lane & 3;
    int wm = w & 1, wn = w >> 1;
    int m0w = wm*64, n0w = wn*64;
    const float* Ab = A + (size_t)b*sA + (size_t)(bi*128)*K;
    const float* Bb = Bm + (size_t)b*sB + bj*256;
    int ar = tid >> 1, ak = (tid & 1)*16;
    int bk = tid >> 3, bn = (tid & 7)*32;

    auto loads = [&](int s, int kt) {
        const float* ga = Ab + (size_t)ar*K + kt + ak;
        unsigned da = su32(AS + s*128*ASTR + ar*ASTR + ak);
#pragma unroll
        for (int i = 0; i < 4; ++i) cpa16(da + 16*i, ga + 4*i);
        const float* gb = Bb + (size_t)(kt + bk)*NN + bn;
        unsigned db = su32(BS + s*32*BSTR2 + bk*BSTR2 + bn);
#pragma unroll
        for (int i = 0; i < 8; ++i) cpa16(db + 16*i, gb + 4*i);
        cpcommit();
    };

    float c[4][8][4];
#pragma unroll
    for (int i = 0; i < 4; ++i)
#pragma unroll
        for (int j = 0; j < 8; ++j)
#pragma unroll
            for (int q = 0; q < 4; ++q) c[i][j][q] = 0.f;

    const int NT = K/32;
    loads(0, 0); loads(1, 32);
    for (int it = 0; it < NT; ++it) {
        if (it < NT-1) cpwait<1>(); else cpwait<0>();
        __syncthreads();
        if (it + 2 < NT) loads((it+2)%3, (it+2)*32);
        const float* Asb = AS + (it%3)*128*ASTR;
        const float* Bsb = BS + (it%3)*32*BSTR2;
#pragma unroll
        for (int ks = 0; ks < 4; ++ks) {
            int k0 = ks*8;
            unsigned af[4][4], bf[8][2];
#pragma unroll
            for (int mt = 0; mt < 4; ++mt) {
                int m = m0w + mt*16 + gid;
                af[mt][0] = __float_as_uint(Asb[(m  )*ASTR + k0 + tg]);
                af[mt][1] = __float_as_uint(Asb[(m+8)*ASTR + k0 + tg]);
                af[mt][2] = __float_as_uint(Asb[(m  )*ASTR + k0 + tg + 4]);
                af[mt][3] = __float_as_uint(Asb[(m+8)*ASTR + k0 + tg + 4]);
            }
#pragma unroll
            for (int nt = 0; nt < 8; ++nt) {
                int n = n0w + nt*8 + gid;
                bf[nt][0] = __float_as_uint(Bsb[(k0 + tg    )*BSTR2 + n]);
                bf[nt][1] = __float_as_uint(Bsb[(k0 + tg + 4)*BSTR2 + n]);
            }
#pragma unroll
            for (int mt = 0; mt < 4; ++mt)
#pragma unroll
                for (int nt = 0; nt < 8; ++nt)
                    mma_tf32(c[mt][nt], af[mt][0], af[mt][1], af[mt][2], af[mt][3],
                             bf[nt][0], bf[nt][1]);
        }
    }
    float* Cb = Cm + (size_t)b*sC + (size_t)(bi*128)*NN + bj*256;
#pragma unroll
    for (int mt = 0; mt < 4; ++mt) {
#pragma unroll
        for (int nt = 0; nt < 8; ++nt) {
            int r0 = m0w + mt*16 + gid;
            int cb = n0w + nt*8 + tg*2;
            int gi0 = bi*128 + r0, gi1 = gi0 + 8;
            int gcb = bj*256 + cb;
            float bz0 = bias ? bias[gcb]     : 0.f;
            float bz1 = bias ? bias[gcb + 1] : 0.f;
            float rs0 = rs ? rs[b*NN + gi0] : 1.f;
            float rs1 = rs ? rs[b*NN + gi1] : 1.f;
            float v00 = (c[mt][nt][0] + bz0)*rs0, v01 = (c[mt][nt][1] + bz1)*rs0;
            float v10 = (c[mt][nt][2] + bz0)*rs1, v11 = (c[mt][nt][3] + bz1)*rs1;
            if (relu) {
                v00 = fmaxf(v00, 0.f); v01 = fmaxf(v01, 0.f);
                v10 = fmaxf(v10, 0.f); v11 = fmaxf(v11, 0.f);
            }
            *(float2*)&Cb[(size_t)r0*NN + cb]     = make_float2(v00, v01);
            *(float2*)&Cb[(size_t)(r0+8)*NN + cb] = make_float2(v10, v11);
        }
    }
}

// -------- wide layer-0 GEMM: concat(P,S,C) @ W0g, LN epilogue, ×dinv ------
__global__ __launch_bounds__(256,1) void k_mm3w(const float* __restrict__ P,
        const float* __restrict__ S, const float* __restrict__ C,
        const float* __restrict__ W0g, const float* __restrict__ vw,
        const float* __restrict__ lnmu, const float* __restrict__ lninv,
        const float* __restrict__ dinv, float* __restrict__ Y) {
    extern __shared__ float sm[];
    float* AS = sm;
    float* BS = sm + 3*128*ASTR;
    int bj = blockIdx.x, bi = blockIdx.y, b = blockIdx.z;
    int tid = threadIdx.x;
    int lane = tid & 31, w = tid >> 5;
    int gid = lane >> 2, tg = lane & 3;
    int wm = w & 1, wn = w >> 1;
    int m0w = wm*64, n0w = wn*64;
    size_t arow = (size_t)b*NN*NN + (size_t)(bi*128)*NN;
    const float* Pb = P + arow;
    const float* Sb = S + arow;
    const float* Cc = C + arow;
    int ar = tid >> 1, ak = (tid & 1)*16;
    int bk = tid >> 3, bn = (tid & 7)*32;

    auto loads = [&](int s, int kt) {
        int seg = kt >> 9, ko = kt & 511;
        const float* base = (seg == 0) ? Pb : ((seg == 1) ? Sb : Cc);
        const float* ga = base + (size_t)ar*NN + ko + ak;
        unsigned da = su32(AS + s*128*ASTR + ar*ASTR + ak);
#pragma unroll
        for (int i = 0; i < 4; ++i) cpa16(da + 16*i, ga + 4*i);
        const float* gb = W0g + (size_t)(kt + bk)*DD + bj*256 + bn;
        unsigned db = su32(BS + s*32*BSTR2 + bk*BSTR2 + bn);
#pragma unroll
        for (int i = 0; i < 8; ++i) cpa16(db + 16*i, gb + 4*i);
        cpcommit();
    };

    float c[4][8][4];
#pragma unroll
    for (int i = 0; i < 4; ++i)
#pragma unroll
        for (int j = 0; j < 8; ++j)
#pragma unroll
            for (int q = 0; q < 4; ++q) c[i][j][q] = 0.f;

    const int NT = INDIM/32;
    loads(0, 0); loads(1, 32);
    for (int it = 0; it < NT; ++it) {
        if (it < NT-1) cpwait<1>(); else cpwait<0>();
        __syncthreads();
        if (it + 2 < NT) loads((it+2)%3, (it+2)*32);
        const float* Asb = AS + (it%3)*128*ASTR;
        const float* Bsb = BS + (it%3)*32*BSTR2;
#pragma unroll
        for (int ks = 0; ks < 4; ++ks) {
            int k0 = ks*8;
            unsigned af[4][4], bf[8][2];
#pragma unroll
            for (int mt = 0; mt < 4; ++mt) {
                int m = m0w + mt*16 + gid;
                af[mt][0] = __float_as_uint(Asb[(m  )*ASTR + k0 + tg]);
                af[mt][1] = __float_as_uint(Asb[(m+8)*ASTR + k0 + tg]);
                af[mt][2] = __float_as_uint(Asb[(m  )*ASTR + k0 + tg + 4]);
                af[mt][3] = __float_as_uint(Asb[(m+8)*ASTR + k0 + tg + 4]);
            }
#pragma unroll
            for (int nt = 0; nt < 8; ++nt) {
                int n = n0w + nt*8 + gid;
                bf[nt][0] = __float_as_uint(Bsb[(k0 + tg    )*BSTR2 + n]);
                bf[nt][1] = __float_as_uint(Bsb[(k0 + tg + 4)*BSTR2 + n]);
            }
#pragma unroll
            for (int mt = 0; mt < 4; ++mt)
#pragma unroll
                for (int nt = 0; nt < 8; ++nt)
                    mma_tf32(c[mt][nt], af[mt][0], af[mt][1], af[mt][2], af[mt][3],
                             bf[nt][0], bf[nt][1]);
        }
    }
    float* Cb = Y + (size_t)b*NN*DD + (size_t)(bi*128)*NN + bj*256;
#pragma unroll
    for (int mt = 0; mt < 4; ++mt) {
#pragma unroll
        for (int nt = 0; nt < 8; ++nt) {
            int r0 = m0w + mt*16 + gid;
            int cb = n0w + nt*8 + tg*2;
            int gi0 = bi*128 + r0, gi1 = gi0 + 8;
            int gj0 = bj*256 + cb, gj1 = gj0 + 1;
            float li0 = lninv[b*NN+gi0], lm0 = lnmu[b*NN+gi0]*li0, d0 = dinv[b*NN+gi0];
            float li1 = lninv[b*NN+gi1], lm1 = lnmu[b*NN+gi1]*li1, d1 = dinv[b*NN+gi1];
            float vv0 = vw[gj0], vv1 = vw[gj1];
            float ww0 = vw[DD+gj0], ww1 = vw[DD+gj1];
            float v00 = (c[mt][nt][0]*li0 - lm0*vv0 + ww0)*d0;
            float v01 = (c[mt][nt][1]*li0 - lm0*vv1 + ww1)*d0;
            float v10 = (c[mt][nt][2]*li1 - lm1*vv0 + ww0)*d1;
            float v11 = (c[mt][nt][3]*li1 - lm1*vv1 + ww1)*d1;
            *(float2*)&Cb[(size_t)r0*NN + cb]     = make_float2(v00, v01);
            *(float2*)&Cb[(size_t)(r0+8)*NN + cb] = make_float2(v10, v11);
        }
    }
}

// ---------------- diag std ----------------
__global__ void k_std2(const float* __restrict__ covP, const float* __restrict__ covS,
                       float* __restrict__ sdP, float* __restrict__ sdS) {
    int e = blockIdx.x*blockDim.x + threadIdx.x;
    if (e >= BB*NN) return;
    int b = e >> 9, n = e & 511;
    size_t d = ((size_t)b*NN + n)*NN + n;
    sdP[e] = sqrtf(fmaxf(covP[d], EPSF));
    sdS[e] = sqrtf(fmaxf(covS[d], EPSF));
}

__global__ void k_stdq(const float* __restrict__ W, float* __restrict__ sdQ) {
    int e = blockIdx.x*blockDim.x + threadIdx.x;
    if (e >= BB*NN) return;
    int b = e >> 9, n = e & 511;
    sdQ[e] = sqrtf(fmaxf(W[((size_t)b*NN + n)*NN + n], EPSF));
}

// ---- blocked GJ inverse, launch A: stage panel rows + invert diag block --
// grid = 16 (batch). One CTA per batch: copy raw panel rows O to g_stage,
// invert the 64x64 diag block, write Binv to g_binv.
__global__ __launch_bounds__(256) void k_invA(const float* __restrict__ srcW,
                                              int p, int first) {
    __shared__ float w_s[64*ILG];
    __shared__ float buf[128];
    int b = blockIdx.x;
    int tid = threadIdx.x;
    int c0 = p*64;
    const float* src = srcW + (size_t)b*NN*NN;
    float* stg = g_stage + (size_t)b*NN*NN;
    for (int e = tid; e < 64*512; e += 256) {
        int i = e >> 9, j = e & 511;
        float v = src[(size_t)(c0+i)*NN + j];
        if (first && (c0+i) == j) v += 0.001f;
        stg[(size_t)(c0+i)*512 + j] = v;
    }
    for (int e = tid; e < 64*64; e += 256) {
        int i = e >> 6, j = e & 63;
        float v = src[(size_t)(c0+i)*NN + c0 + j];
        if (first && i == j) v += 0.001f;
        w_s[i*ILG + j] = v;
    }
    __syncthreads();
    for (int k = 0; k < 64; ++k) {
        if (tid < 64) buf[tid] = w_s[tid*ILG + k];
        else if (tid < 128) buf[64 + (tid-64)] = w_s[k*ILG + (tid-64)];
        __syncthreads();
        float d = 1.0f / buf[64 + k];
        for (int e = tid; e < 64*64; e += 256) {
            int i = e >> 6, j = e & 63;
            float f = buf[i], rk = buf[64 + j];
            float nv;
            if (i == k) nv = (j == k) ? d : rk*d;
            else        nv = (j == k) ? (-f*d) : (w_s[i*ILG+j] - f*(rk*d));
            w_s[i*ILG+j] = nv;
        }
        __syncthreads();
    }
    for (int e = tid; e < 64*64; e += 256)
        g_binv[(size_t)b*4096 + e] = w_s[(e>>6)*ILG + (e&63)];
}

// ---- blocked GJ inverse, launch B: per (rowblock, batch) panel update ----
// G = F@Binv (owner: G = Binv); rows <- rows - G@O (owner: G@O);
// panel cols <- -G (owner: Binv). O chunks cp.async double-buffered.
__global__ __launch_bounds__(256,2) void k_invB(const float* __restrict__ srcW,
        float* __restrict__ W, int p, int first) {
    extern __shared__ float smb[];
    float* bv = smb;               // 64*ILG  (Binv)
    float* gh = bv + 64*ILG;       // 64*ILG
    float* gl = gh + 64*ILG;       // 64*ILG
    float* os = gl + 64*ILG;       // 2 * 64*ILG (F, then O chunks)
    int rb = blockIdx.x, b = blockIdx.y;
    int r0 = rb*64, c0 = p*64;
    bool own = (rb == p);
    int tid = threadIdx.x;
    int lane = tid & 31, w = tid >> 5;
    int gid = lane >> 2, tg = lane & 3;
    const float* src = srcW + (size_t)b*NN*NN;
    float* Wb = W + (size_t)b*NN*NN;
    const float* stg = g_stage + (size_t)b*NN*NN;
    const float* binv = g_binv + (size_t)b*4096;

    for (int e = tid; e < 64*64; e += 256)
        bv[(e>>6)*ILG + (e&63)] = binv[e];
    __syncthreads();

    if (own) {
        for (int e = tid; e < 64*64; e += 256) {
            int i = e >> 6, j = e & 63;
            float f = bv[i*ILG + j];
            unsigned hi, lo; tfsplit(f, hi, lo);
            gh[i*ILG + j] = __uint_as_float(hi);
            gl[i*ILG + j] = __uint_as_float(lo);
            Wb[(size_t)(r0+i)*NN + c0 + j] = f;
        }
        __syncthreads();
    } else {
        // F into os buffer 0
        for (int e = tid; e < 64*64; e += 256) {
            int i = e >> 6, j = e & 63;
            os[i*ILG + j] = src[(size_t)(r0+i)*NN + c0 + j];
        }
        __syncthreads();
        int n = w*8 + gid;
        float acc[4][4];
#pragma unroll
        for (int i = 0; i < 4; ++i)
#pragma unroll
            for (int q = 0; q < 4; ++q) acc[i][q] = 0.f;
#pragma unroll 2
        for (int ks = 0; ks < 8; ++ks) {
            int k0 = ks*8;
            unsigned ahi[4][4], alo[4][4];
#pragma unroll
            for (int mt = 0; mt < 4; ++mt) {
                int m = mt*16 + gid;
                tfsplit(os[m*ILG + k0 + tg],        ahi[mt][0], alo[mt][0]);
                tfsplit(os[(m+8)*ILG + k0 + tg],    ahi[mt][1], alo[mt][1]);
                tfsplit(os[m*ILG + k0 + tg + 4],    ahi[mt][2], alo[mt][2]);
                tfsplit(os[(m+8)*ILG + k0 + tg + 4],ahi[mt][3], alo[mt][3]);
            }
            unsigned bhi[2], blo[2];
            tfsplit(bv[(k0+tg  )*ILG + n], bhi[0], blo[0]);
            tfsplit(bv[(k0+tg+4)*ILG + n], bhi[1], blo[1]);
#pragma unroll
            for (int mt = 0; mt < 4; ++mt) {
                mma_tf32(acc[mt], ahi[mt][0],ahi[mt][1],ahi[mt][2],ahi[mt][3], bhi[0],bhi[1]);
                mma_tf32(acc[mt], ahi[mt][0],ahi[mt][1],ahi[mt][2],ahi[mt][3], blo[0],blo[1]);
                mma_tf32(acc[mt], alo[mt][0],alo[mt][1],alo[mt][2],alo[mt][3], bhi[0],bhi[1]);
            }
        }
        __syncthreads();   // all F reads done before os reuse
#pragma unroll
        for (int mt = 0; mt < 4; ++mt) {
            int r = mt*16 + gid;
            int cpos = w*8 + tg*2;
            *(float2*)&Wb[(size_t)(r0+r)*NN + c0 + cpos] = make_float2(-acc[mt][0], -acc[mt][1]);
            *(float2*)&Wb[(size_t)(r0+r+8)*NN + c0 + cpos] = make_float2(-acc[mt][2], -acc[mt][3]);
            unsigned hi, lo;
            tfsplit(acc[mt][0], hi, lo);
            gh[r*ILG + cpos]   = __uint_as_float(hi); gl[r*ILG + cpos]   = __uint_as_float(lo);
            tfsplit(acc[mt][1], hi, lo);
            gh[r*ILG + cpos+1] = __uint_as_float(hi); gl[r*ILG + cpos+1] = __uint_as_float(lo);
            tfsplit(acc[mt][2], hi, lo);
            gh[(r+8)*ILG + cpos]   = __uint_as_float(hi); gl[(r+8)*ILG + cpos]   = __uint_as_float(lo);
            tfsplit(acc[mt][3], hi, lo);
            gh[(r+8)*ILG + cpos+1] = __uint_as_float(hi); gl[(r+8)*ILG + cpos+1] = __uint_as_float(lo);
        }
        __syncthreads();
    }

    // ---- update 7 non-panel chunks, O double-buffered from stage ----
    int cl[7]; int nc = 0;
    for (int ch = 0; ch < 8; ++ch) if (ch != p) cl[nc++] = ch;
    {
        int ch = cl[0];
#pragma unroll
        for (int i4 = 0; i4 < 4; ++i4) {
            int idx = tid + i4*256;
            int row = idx >> 4, c4 = (idx & 15)*4;
            cpa16(su32(os + row*ILG + c4),
                  stg + (size_t)(c0+row)*512 + ch*64 + c4);
        }
        cpcommit();
    }
    for (int t = 0; t < 7; ++t) {
        cpwait<0>();
        __syncthreads();
        if (t + 1 < 7) {
            int chn = cl[t+1];
            float* dst = os + ((t+1)&1)*(64*ILG);
#pragma unroll
            for (int i4 = 0; i4 < 4; ++i4) {
                int idx = tid + i4*256;
                int row = idx >> 4, c4 = (idx & 15)*4;
                cpa16(su32(dst + row*ILG + c4),
                      stg + (size_t)(c0+row)*512 + chn*64 + c4);
            }
            cpcommit();
        }
        const float* ob = os + (t&1)*(64*ILG);
        int ch = cl[t];
        int n = w*8 + gid;
        float acc[4][4];
#pragma unroll
        for (int i = 0; i < 4; ++i)
#pragma unroll
            for (int q = 0; q < 4; ++q) acc[i][q] = 0.f;
#pragma unroll
        for (int ks = 0; ks < 8; ++ks) {
            int k0 = ks*8;
            unsigned ahi[4][4], alo[4][4];
#pragma unroll
            for (int mt = 0; mt < 4; ++mt) {
                int m = mt*16 + gid;
                ahi[mt][0] = __float_as_uint(gh[m*ILG + k0 + tg]);
                alo[mt][0] = __float_as_uint(gl[m*ILG + k0 + tg]);
                ahi[mt][1] = __float_as_uint(gh[(m+8)*ILG + k0 + tg]);
                alo[mt][1] = __float_as_uint(gl[(m+8)*ILG + k0 + tg]);
                ahi[mt][2] = __float_as_uint(gh[m*ILG + k0 + tg + 4]);
                alo[mt][2] = __float_as_uint(gl[m*ILG + k0 + tg + 4]);
                ahi[mt][3] = __float_as_uint(gh[(m+8)*ILG + k0 + tg + 4]);
                alo[mt][3] = __float_as_uint(gl[(m+8)*ILG + k0 + tg + 4]);
            }
            unsigned bhi[2], blo[2];
            tfsplit(ob[(k0+tg  )*ILG + n], bhi[0], blo[0]);
            tfsplit(ob[(k0+tg+4)*ILG + n], bhi[1], blo[1]);
#pragma unroll
            for (int mt = 0; mt < 4; ++mt) {
                mma_tf32(acc[mt], ahi[mt][0],ahi[mt][1],ahi[mt][2],ahi[mt][3], bhi[0],bhi[1]);
                mma_tf32(acc[mt], ahi[mt][0],ahi[mt][1],ahi[mt][2],ahi[mt][3], blo[0],blo[1]);
                mma_tf32(acc[mt], alo[mt][0],alo[mt][1],alo[mt][2],alo[mt][3], bhi[0],bhi[1]);
            }
        }
#pragma unroll
        for (int mt = 0; mt < 4; ++mt) {
            int r = mt*16 + gid;
            int gc = ch*64 + w*8 + tg*2;
            if (own) {
                *(float2*)&Wb[(size_t)(r0+r)*NN + gc]   = make_float2(acc[mt][0], acc[mt][1]);
                *(float2*)&Wb[(size_t)(r0+r+8)*NN + gc] = make_float2(acc[mt][2], acc[mt][3]);
            } else {
                float o0 = src[(size_t)(r0+r)*NN + gc];
                float o1 = src[(size_t)(r0+r)*NN + gc + 1];
                float o2 = src[(size_t)(r0+r+8)*NN + gc];
                float o3 = src[(size_t)(r0+r+8)*NN + gc + 1];
                if (first) {
                    if (r0+r   == gc  ) o0 += 0.001f;
                    if (r0+r   == gc+1) o1 += 0.001f;
                    if (r0+r+8 == gc  ) o2 += 0.001f;
                    if (r0+r+8 == gc+1) o3 += 0.001f;
                }
                *(float2*)&Wb[(size_t)(r0+r)*NN + gc]   = make_float2(o0 - acc[mt][0], o1 - acc[mt][1]);
                *(float2*)&Wb[(size_t)(r0+r+8)*NN + gc] = make_float2(o2 - acc[mt][2], o3 - acc[mt][3]);
            }
        }
        __syncthreads();
    }
}

// ------- fused corr + partial-corr + pairwise dots -------
__global__ void k_pcdots(const float* __restrict__ covP, const float* __restrict__ sdP,
                         const float* __restrict__ covS, const float* __restrict__ sdS,
                         const float* __restrict__ prec, const float* __restrict__ sdQ,
                         float* __restrict__ P, float* __restrict__ S,
                         float* __restrict__ C, float* __restrict__ parts) {
    __shared__ float red[256];
    float t1 = tanhf(1.f);
    int b = blockIdx.y, ch = blockIdx.x;
    size_t base = (size_t)b*NN*NN + (size_t)ch*8192;
    float a[6] = {0,0,0,0,0,0};
    for (int e0 = threadIdx.x; e0 < 8192; e0 += 256) {
        size_t e = base + e0;
        int r = ch*8192 + e0; int i = r >> 9, j = r & 511;
        float vp, vs, c;
        if (i == j) { vp = 1.f; vs = 1.f; c = t1; }
        else {
            vp = covP[e] / (sdP[b*NN+i]*sdP[b*NN+j]);
            if (!isfinite(vp)) vp = 0.f;
            vs = covS[e] / (sdS[b*NN+i]*sdS[b*NN+j]);
            if (!isfinite(vs)) vs = 0.f;
            c = tanhf(-prec[e] / (sdQ[b*NN+i]*sdQ[b*NN+j]));
        }
        P[e] = vp; S[e] = vs; C[e] = c;
        a[0] += vp*vp; a[1] += vs*vs; a[2] += c*c;
        a[3] += vp*vs; a[4] += vp*c; a[5] += vs*c;
    }
    for (int v = 0; v < 6; ++v) {
        red[threadIdx.x] = a[v]; __syncthreads();
        for (int o = 128; o > 0; o >>= 1) {
            if (threadIdx.x < o) red[threadIdx.x] += red[threadIdx.x + o];
            __syncthreads();
        }
        if (threadIdx.x == 0) parts[((size_t)b*32 + ch)*6 + v] = red[0];
        __syncthreads();
    }
}

// ---------------- sims + softmax alphas ----------------
__global__ void k_sims(const float* __restrict__ parts, const float* __restrict__ gamma,
                       float* __restrict__ alph) {
    int b = threadIdx.x;
    if (b >= BB) return;
    float F[6] = {0,0,0,0,0,0};
    for (int ch = 0; ch < 32; ++ch)
        for (int v = 0; v < 6; ++v) F[v] += parts[((size_t)b*32 + ch)*6 + v];
    float dC = tanhf(1.f);
    float dv[3] = {1.f, 1.f, dC};
    float D[3][3];
    D[0][0] = (F[0] - NN*dv[0]*dv[0]) * 0.5f;
    D[1][1] = (F[1] - NN*dv[1]*dv[1]) * 0.5f;
    D[2][2] = (F[2] - NN*dv[2]*dv[2]) * 0.5f;
    D[0][1] = D[1][0] = (F[3] - NN*dv[0]*dv[1]) * 0.5f;
    D[0][2] = D[2][0] = (F[4] - NN*dv[0]*dv[2]) * 0.5f;
    D[1][2] = D[2][1] = (F[5] - NN*dv[1]*dv[2]) * 0.5f;
    float rowsum[3], tot2 = 0.f;
    for (int v = 0; v < 3; ++v) {
        rowsum[v] = D[v][0] + D[v][1] + D[v][2];
        tot2 += rowsum[v];
    }
    float sims[3];
    for (int v = 0; v < 3; ++v) {
        float num = 0.5f * (rowsum[v] - D[v][v]);
        float nv = sqrtf(fmaxf(D[v][v], 0.f));
        float oo = 0.25f * (tot2 - 2.f*rowsum[v] + D[v][v]);
        float no = sqrtf(fmaxf(oo, 0.f));
        float den = fmaxf(nv, EPSF) * fmaxf(no, EPSF);
        sims[v] = num / den;
    }
    float g = gamma[0];
    float m = fmaxf(g*sims[0], fmaxf(g*sims[1], g*sims[2]));
    float e0 = expf(g*sims[0]-m), e1 = expf(g*sims[1]-m), e2 = expf(g*sims[2]-m);
    float si = 1.f / (e0 + e1 + e2);
    alph[b*4+0] = e0*si; alph[b*4+1] = e1*si; alph[b*4+2] = e2*si;
}

// ------- fuse + rowsum + LN row stats -------
__global__ __launch_bounds__(128) void k_fuse_rs(const float* __restrict__ P,
                      const float* __restrict__ S, const float* __restrict__ C,
                      const float* __restrict__ alph, float* __restrict__ Af,
                      float* __restrict__ dinv, float* __restrict__ lnmu,
                      float* __restrict__ lninv) {
    __shared__ float red[128];
    int bn = blockIdx.x;
    int b = bn >> 9, i = bn & 511;
    float aP = alph[b*4+0], aS = alph[b*4+1], aC = alph[b*4+2];
    size_t base = (size_t)bn*NN;
    float s = 0.f, s1 = 0.f, s2 = 0.f;
    for (int j = threadIdx.x; j < NN; j += 128) {
        float p = P[base+j], sv = S[base+j], cv = C[base+j];
        float v = aP*p + aS*sv + aC*cv;
        if (j == i) v = 1.f;
        Af[base+j] = v;
        s += v;
        s1 += p + sv + cv;
        s2 += p*p + sv*sv + cv*cv;
    }
    red[threadIdx.x] = s; __syncthreads();
    for (int o = 64; o > 0; o >>= 1) {
        if (threadIdx.x < o) red[threadIdx.x] += red[threadIdx.x + o];
        __syncthreads();
    }
    if (threadIdx.x == 0) dinv[bn] = rsqrtf(fmaxf(red[0], EPSF));
    __syncthreads();
    red[threadIdx.x] = s1; __syncthreads();
    for (int o = 64; o > 0; o >>= 1) {
        if (threadIdx.x < o) red[threadIdx.x] += red[threadIdx.x + o];
        __syncthreads();
    }
    float mu = red[0] * (1.f/INDIM);
    __syncthreads();
    red[threadIdx.x] = s2; __syncthreads();
    for (int o = 64; o > 0; o >>= 1) {
        if (threadIdx.x < o) red[threadIdx.x] += red[threadIdx.x + o];
        __syncthreads();
    }
    if (threadIdx.x == 0) {
        lnmu[bn] = mu;
        lninv[bn] = rsqrtf(red[0]*(1.f/INDIM) - mu*mu + 1e-5f);
    }
}

// ---------------- head ----------------
__global__ void k_head1(const float* __restrict__ H, float* __restrict__ part) {
    int b = blockIdx.y, ch = blockIdx.x, d = threadIdx.x;
    float s = 0.f;
#pragma unroll 8
    for (int r = 0; r < 32; ++r)
        s += H[((size_t)b*NN + ch*32 + r)*DD + d];
    part[((size_t)b*16 + ch)*DD + d] = s;
}

__global__ void k_head2(const float* __restrict__ part, const float* __restrict__ Wc,
                        const float* __restrict__ bc, float* __restrict__ out) {
    __shared__ float red[512];
    int b = blockIdx.x, d = threadIdx.x;
    float s = 0.f;
    for (int ch = 0; ch < 16; ++ch) s += part[((size_t)b*16 + ch)*DD + d];
    red[d] = (s * (1.f/NN)) * Wc[d];
    __syncthreads();
    for (int o = 256; o > 0; o >>= 1) {
        if (d < o) red[d] += red[d + o];
        __syncthreads();
    }
    if (d == 0) out[b] = 1.f / (1.f + expf(-(red[0] + bc[0])));
}

// ---------------- host ----------------
extern "C" void kernel_launch(void* const* d_in, const int* in_sizes, int n_in,
                              void* d_out, int out_size) {
    const float* x    = (const float*)d_in[0];
    const float* gam  = (const float*)d_in[1];
    const float* lng  = (const float*)d_in[2];
    const float* lnb  = (const float*)d_in[3];
    const float* W0   = (const float*)d_in[4];
    const float* b0   = (const float*)d_in[5];
    const float* W1   = (const float*)d_in[6];
    const float* b1   = (const float*)d_in[7];
    const float* W2   = (const float*)d_in[8];
    const float* b2   = (const float*)d_in[9];
    const float* Wc   = (const float*)d_in[10];
    const float* bc   = (const float*)d_in[11];
    float* out = (float*)d_out;

    float *pXt,*pRc,*pMu,*pCovP,*pCovS,*pP,*pS,*pPrec,*pC,*pAf,*pY,*pH;
    float *pSdP,*pSdS,*pSdQ,*pParts,*pAl,*pDinv,*pStage,*pLnmu,*pLninv,*pW0g,*pVw,*pVwp;
    cudaGetSymbolAddress((void**)&pXt,   g_xt);
    cudaGetSymbolAddress((void**)&pRc,   g_rc);
    cudaGetSymbolAddress((void**)&pMu,   g_mu);
    cudaGetSymbolAddress((void**)&pCovP, g_covP);
    cudaGetSymbolAddress((void**)&pCovS, g_covS);
    cudaGetSymbolAddress((void**)&pP,    g_P);
    cudaGetSymbolAddress((void**)&pS,    g_S);
    cudaGetSymbolAddress((void**)&pPrec, g_prec);
    cudaGetSymbolAddress((void**)&pC,    g_C);
    cudaGetSymbolAddress((void**)&pAf,   g_Af);
    cudaGetSymbolAddress((void**)&pY,    g_Ybuf);
    cudaGetSymbolAddress((void**)&pH,    g_Hbuf);
    cudaGetSymbolAddress((void**)&pSdP,  g_sdP);
    cudaGetSymbolAddress((void**)&pSdS,  g_sdS);
    cudaGetSymbolAddress((void**)&pSdQ,  g_sdQ);
    cudaGetSymbolAddress((void**)&pParts,g_parts);
    cudaGetSymbolAddress((void**)&pAl,   g_alph);
    cudaGetSymbolAddress((void**)&pDinv, g_dinv);
    cudaGetSymbolAddress((void**)&pStage,g_stage);
    cudaGetSymbolAddress((void**)&pLnmu, g_lnmu);
    cudaGetSymbolAddress((void**)&pLninv,g_lninv);
    cudaGetSymbolAddress((void**)&pW0g,  g_W0g);
    cudaGetSymbolAddress((void**)&pVw,   g_vw);
    cudaGetSymbolAddress((void**)&pVwp,  g_vwp);

    const int GRAM_SMEM = (6*128*ASTR) * 4;
    const int MMW_SMEM  = (3*128*ASTR + 3*32*BSTR2) * 4;
    const int INVB_SMEM = (5*64*ILG) * 4;
    cudaFuncSetAttribute(k_gram_t, cudaFuncAttributeMaxDynamicSharedMemorySize, GRAM_SMEM);
    cudaFuncSetAttribute(k_mm_w,   cudaFuncAttributeMaxDynamicSharedMemorySize, MMW_SMEM);
    cudaFuncSetAttribute(k_mm3w,   cudaFuncAttributeMaxDynamicSharedMemorySize, MMW_SMEM);
    cudaFuncSetAttribute(k_invB,   cudaFuncAttributeMaxDynamicSharedMemorySize, INVB_SMEM);

    const float GSCALE = (float)(1.0 / (1023.0 + 1e-8));

    k_transpose<<<dim3(NN/32, TT/32, BB), dim3(32,8)>>>(x, pXt);          // 0
    k_sort<<<BB*NN, 512>>>(pXt, pRc, pMu);                                 // 1
    k_gram_t<<<dim3(10, BB, 2), 256, GRAM_SMEM>>>(pXt, pRc, pMu,
                                                  pCovP, pCovS, GSCALE);   // 2
    // idx 3 = first k_invA -> profiled; validates the serial-GJ cost model
    for (int p = 0; p < 8; ++p) {
        const float* srcW = (p == 0) ? pCovP : pPrec;
        k_invA<<<16, 256>>>(srcW, p, p == 0);
        k_invB<<<dim3(8, 16), 256, INVB_SMEM>>>(srcW, pPrec, p, p == 0);
    }
    k_stdq<<<(BB*NN+255)/256, 256>>>(pPrec, pSdQ);
    k_std2<<<(BB*NN+255)/256, 256>>>(pCovP, pCovS, pSdP, pSdS);
    k_prepw0<<<512, 256>>>(W0, lng, pW0g);
    k_prepvw<<<96, 512>>>(W0, lng, lnb, pVwp);
    k_vwred<<<1, 512>>>(pVwp, b0, pVw);

    k_pcdots<<<dim3(32, BB), 256>>>(pCovP, pSdP, pCovS, pSdS, pPrec, pSdQ,
                                    pP, pS, pC, pParts);
    k_sims<<<1, 32>>>(pParts, gam, pAl);
    k_fuse_rs<<<BB*NN, 128>>>(pP, pS, pC, pAl, pAf, pDinv, pLnmu, pLninv);

    long long sM = (long long)NN*DD, sA2 = (long long)NN*NN;
    k_mm3w<<<dim3(2,4,BB), 256, MMW_SMEM>>>(pP, pS, pC, pW0g, pVw, pLnmu, pLninv, pDinv, pY);
    k_mm_w<<<dim3(2,4,BB), 256, MMW_SMEM>>>(pAf, sA2, pY, sM, (const float*)0, pDinv, pH, sM, DD, 1);
    k_mm_w<<<dim3(2,4,BB), 256, MMW_SMEM>>>(pH,  sM,  W1, 0LL, b1, pDinv, pY, sM, DD, 0);
    k_mm_w<<<dim3(2,4,BB), 256, MMW_SMEM>>>(pAf, sA2, pY, sM, (const float*)0, pDinv, pH, sM, DD, 1);
    k_mm_w<<<dim3(2,4,BB), 256, MMW_SMEM>>>(pH,  sM,  W2, 0LL, b2, pDinv, pY, sM, DD, 0);
    k_mm_w<<<dim3(2,4,BB), 256, MMW_SMEM>>>(pAf, sA2, pY, sM, (const float*)0, pDinv, pH, sM, DD, 1);

    k_head1<<<dim3(16, BB), 512>>>(pH, pStage);
    k_head2<<<BB, 512>>>(pStage, Wc, bc, out);

    (void)in_sizes; (void)n_in; (void)out_size;
}

// round 16
// speedup vs baseline: 1.1347x; 1.1347x over previous
#include <cuda_runtime.h>
#include <math.h>

#define BB 16
#define TT 1024
#define NN 512
#define DD 512
#define INDIM 1536
#define EPSF 1e-8f

// ---------------- device scratch (no allocations allowed) ----------------
__device__ float g_xt  [BB*NN*TT];
__device__ float g_rc  [BB*NN*TT];
__device__ float g_mu  [BB*NN];
__device__ float g_covP[BB*NN*NN];
__device__ float g_covS[BB*NN*NN];
__device__ float g_P   [BB*NN*NN];
__device__ float g_S   [BB*NN*NN];
__device__ float g_prec[BB*NN*NN];
__device__ float g_C   [BB*NN*NN];
__device__ float g_Af  [BB*NN*NN];
__device__ float g_Ybuf[BB*NN*DD];
__device__ float g_Hbuf[BB*NN*DD];
__device__ float g_stage[BB*NN*NN];
__device__ int   g_flags[BB*8];
__device__ float g_sdP [BB*NN];
__device__ float g_sdS [BB*NN];
__device__ float g_sdQ [BB*NN];
__device__ float g_parts[BB*32*6];
__device__ float g_alph[BB*4];
__device__ float g_dinv[BB*NN];
__device__ float g_lnmu[BB*NN];
__device__ float g_lninv[BB*NN];
__device__ float g_W0g [INDIM*DD];
__device__ float g_vw  [2*DD];
__device__ float g_vwp [96*2*DD];

__constant__ int c_BI[10] = {0,1,1,2,2,2,3,3,3,3};
__constant__ int c_BJ[10] = {0,0,1,0,1,2,0,1,2,3};

// ---------------- tf32 mma helpers ----------------
__device__ __forceinline__ unsigned su32(const void* p) {
    return (unsigned)__cvta_generic_to_shared(p);
}
__device__ __forceinline__ void cpa16(unsigned dst, const void* src) {
    asm volatile("cp.async.cg.shared.global [%0], [%1], 16;" :: "r"(dst), "l"(src));
}
__device__ __forceinline__ void cpcommit() { asm volatile("cp.async.commit_group;"); }
template<int N> __device__ __forceinline__ void cpwait() {
    asm volatile("cp.async.wait_group %0;" :: "n"(N) : "memory");
}
__device__ __forceinline__ void mma_tf32(float* c,
        unsigned a0, unsigned a1, unsigned a2, unsigned a3,
        unsigned b0, unsigned b1) {
    asm volatile("mma.sync.aligned.m16n8k8.row.col.f32.tf32.tf32.f32 "
        "{%0,%1,%2,%3}, {%4,%5,%6,%7}, {%8,%9}, {%0,%1,%2,%3};"
        : "+f"(c[0]), "+f"(c[1]), "+f"(c[2]), "+f"(c[3])
        : "r"(a0), "r"(a1), "r"(a2), "r"(a3), "r"(b0), "r"(b1));
}
__device__ __forceinline__ unsigned f2tf(float f) {
    unsigned r; asm("cvt.rna.tf32.f32 %0, %1;" : "=r"(r) : "f"(f)); return r;
}
__device__ __forceinline__ void tfsplit(float f, unsigned& hi, unsigned& lo) {
    hi = f2tf(f);
    lo = f2tf(f - __uint_as_float(hi));
}

#define ASTR 36
#define BSTR2 264   // 256 + 8 pad, conflict-free B frags for the wide tile
#define IAST 520    // k_inv a_s row stride (512 + 8)
#define IWST 68     // k_inv w_s row stride (64 + 4)
#define IPST 136    // k_inv p_s chunk row stride (128 + 8)

// ---- warp-local 32x32 Gauss-Jordan inverse (registers + shfl, no bar) ----
__device__ __forceinline__ void inv32_shfl(float* base, int stride) {
    int lane = threadIdx.x & 31;
    float a[32];
#pragma unroll
    for (int j = 0; j < 32; ++j) a[j] = base[lane*stride + j];
    for (int k = 0; k < 32; ++k) {
        float f = 0.f;
#pragma unroll
        for (int j = 0; j < 32; ++j) if (j == k) f = a[j];
        float pk = __shfl_sync(0xffffffffu, f, k);
        float d = 1.0f / pk;
#pragma unroll
        for (int j = 0; j < 32; ++j) {
            float pj = __shfl_sync(0xffffffffu, a[j], k);
            float pjd = pj * d;
            float nv = a[j] - f*pjd;
            if (j == k) nv = -f*d;
            if (lane == k) nv = (j == k) ? d : pjd;
            a[j] = nv;
        }
    }
#pragma unroll
    for (int j = 0; j < 32; ++j) base[lane*stride + j] = a[j];
}

// ---------------- transpose (+ GJ flag reset) ----------------
__global__ void k_transpose(const float* __restrict__ x, float* __restrict__ xt) {
    __shared__ float tile[32][33];
    int b = blockIdx.z;
    int n0 = blockIdx.x * 32, t0 = blockIdx.y * 32;
    if (blockIdx.x == 0 && blockIdx.y == 0 && blockIdx.z == 0) {
        int t = threadIdx.y*32 + threadIdx.x;
        if (t < BB*8) g_flags[t] = 0;
    }
    for (int r = threadIdx.y; r < 32; r += 8)
        tile[r][threadIdx.x] = x[((size_t)b*TT + t0 + r)*NN + n0 + threadIdx.x];
    __syncthreads();
    for (int r = threadIdx.y; r < 32; r += 8)
        xt[((size_t)b*NN + n0 + r)*TT + t0 + threadIdx.x] = tile[threadIdx.x][r];
}

// ---------------- bitonic argsort -> centered ranks (+ mean) --------------
__global__ __launch_bounds__(512) void k_sort(const float* __restrict__ xt,
                                              float* __restrict__ rc,
                                              float* __restrict__ mu) {
    __shared__ unsigned long long keys[1024];
    __shared__ float red[512];
    int bn = blockIdx.x;
    const float* row = xt + (size_t)bn*TT;
    float s = 0.f;
    for (int t = threadIdx.x; t < 1024; t += 512) {
        float v = row[t];
        s += v;
        unsigned u = __float_as_uint(v);
        u = (u & 0x80000000u) ? ~u : (u | 0x80000000u);
        keys[t] = ((unsigned long long)u << 32) | (unsigned)t;
    }
    red[threadIdx.x] = s; __syncthreads();
    for (int o = 256; o > 0; o >>= 1) {
        if (threadIdx.x < o) red[threadIdx.x] += red[threadIdx.x + o];
        __syncthreads();
    }
    if (threadIdx.x == 0) mu[bn] = red[0] * (1.f / TT);
    for (int k2 = 2; k2 <= 1024; k2 <<= 1)
        for (int j = k2 >> 1; j > 0; j >>= 1) {
            int t = threadIdx.x;
            int i = ((t & ~(j-1)) << 1) | (t & (j-1));
            int l = i | j;
            unsigned long long a = keys[i], b2 = keys[l];
            if ((a > b2) == ((i & k2) == 0)) { keys[i] = b2; keys[l] = a; }
            __syncthreads();
        }
    float* out = rc + (size_t)bn*TT;
    for (int p = threadIdx.x; p < 1024; p += 512) {
        int idx = (int)(keys[p] & 0xffffffffu);
        out[idx] = (float)(p+1) - 512.5f;
    }
}

// ---------------- W0g = ln_g ⊙row W0 ----------------
__global__ void k_prepw0(const float* __restrict__ W0, const float* __restrict__ lng,
                         float* __restrict__ W0g) {
    for (int e = blockIdx.x*blockDim.x + threadIdx.x; e < INDIM*DD; e += gridDim.x*blockDim.x)
        W0g[e] = lng[e >> 9] * W0[e];
}

// ---------------- v,w partials (96 blocks of 16 rows) ----------------
__global__ __launch_bounds__(512) void k_prepvw(const float* __restrict__ W0,
        const float* __restrict__ lng, const float* __restrict__ lnb,
        float* __restrict__ vwp) {
    int j = threadIdx.x, bz = blockIdx.x;
    float v = 0.f, w = 0.f;
#pragma unroll
    for (int q = 0; q < 16; ++q) {
        int c = bz*16 + q;
        float wv = W0[(size_t)c*DD + j];
        v += lng[c]*wv; w += lnb[c]*wv;
    }
    vwp[(bz*2+0)*DD + j] = v;
    vwp[(bz*2+1)*DD + j] = w;
}
__global__ __launch_bounds__(512) void k_vwred(const float* __restrict__ vwp,
        const float* __restrict__ b0, float* __restrict__ vw) {
    int j = threadIdx.x;
    float v = 0.f, w = 0.f;
    for (int bz = 0; bz < 96; ++bz) {
        v += vwp[(bz*2+0)*DD + j];
        w += vwp[(bz*2+1)*DD + j];
    }
    vw[j] = v; vw[DD + j] = w + b0[j];
}

// ---------------- tf32 Gram ----------------
__global__ __launch_bounds__(256,2) void k_gram_t(const float* __restrict__ xt,
        const float* __restrict__ rc, const float* __restrict__ mu,
        float* __restrict__ covP, float* __restrict__ covS, float scale) {
    extern __shared__ float sm[];
    float* AS = sm;
    float* BS = sm + 3*128*ASTR;
    int p = blockIdx.x, b = blockIdx.y, z = blockIdx.z;
    int bi = c_BI[p], bj = c_BJ[p];
    int tid = threadIdx.x;
    int lane = tid & 31, w = tid >> 5;
    int gid = lane >> 2, tg = lane & 3;
    int wm = w & 1, wn = w >> 1;
    int m0w = wm*64, n0w = wn*32;
    const float* src = (z ? rc : xt) + (size_t)b*NN*TT;
    const float* Ab = src + (size_t)(bi*128)*TT;
    const float* Bb = src + (size_t)(bj*128)*TT;
    int ar = tid >> 1, ak = (tid & 1)*16;

    auto loads = [&](int s, int kt) {
        const float* ga = Ab + (size_t)ar*TT + kt + ak;
        unsigned da = su32(AS + s*128*ASTR + ar*ASTR + ak);
        const float* gb = Bb + (size_t)ar*TT + kt + ak;
        unsigned db = su32(BS + s*128*ASTR + ar*ASTR + ak);
#pragma unroll
        for (int i = 0; i < 4; ++i) { cpa16(da + 16*i, ga + 4*i); cpa16(db + 16*i, gb + 4*i); }
        cpcommit();
    };

    float c[4][4][4];
#pragma unroll
    for (int i = 0; i < 4; ++i)
#pragma unroll
        for (int j = 0; j < 4; ++j)
#pragma unroll
            for (int q = 0; q < 4; ++q) c[i][j][q] = 0.f;

    const int NT = TT/32;
    loads(0, 0); loads(1, 32);
    for (int it = 0; it < NT; ++it) {
        if (it < NT-1) cpwait<1>(); else cpwait<0>();
        __syncthreads();
        if (it + 2 < NT) loads((it+2)%3, (it+2)*32);
        const float* Asb = AS + (it%3)*128*ASTR;
        const float* Bsb = BS + (it%3)*128*ASTR;
#pragma unroll
        for (int ks = 0; ks < 4; ++ks) {
            int k0 = ks*8;
            unsigned af[4][4], bf[4][2];
#pragma unroll
            for (int mt = 0; mt < 4; ++mt) {
                int m = m0w + mt*16 + gid;
                af[mt][0] = __float_as_uint(Asb[(m  )*ASTR + k0 + tg]);
                af[mt][1] = __float_as_uint(Asb[(m+8)*ASTR + k0 + tg]);
                af[mt][2] = __float_as_uint(Asb[(m  )*ASTR + k0 + tg + 4]);
                af[mt][3] = __float_as_uint(Asb[(m+8)*ASTR + k0 + tg + 4]);
            }
#pragma unroll
            for (int nt = 0; nt < 4; ++nt) {
                int n = n0w + nt*8 + gid;
                bf[nt][0] = __float_as_uint(Bsb[n*ASTR + k0 + tg]);
                bf[nt][1] = __float_as_uint(Bsb[n*ASTR + k0 + tg + 4]);
            }
#pragma unroll
            for (int mt = 0; mt < 4; ++mt)
#pragma unroll
                for (int nt = 0; nt < 4; ++nt)
                    mma_tf32(c[mt][nt], af[mt][0], af[mt][1], af[mt][2], af[mt][3],
                             bf[nt][0], bf[nt][1]);
        }
    }
    float* Cb = (z ? covS : covP) + (size_t)b*NN*NN;
    const float* mub = mu + b*NN;
#pragma unroll
    for (int mt = 0; mt < 4; ++mt) {
#pragma unroll
        for (int nt = 0; nt < 4; ++nt) {
            int r0 = m0w + mt*16 + gid;
            int cb = n0w + nt*8 + tg*2;
            int gi0 = bi*128 + r0, gi1 = gi0 + 8;
            int gj0 = bj*128 + cb, gj1 = gj0 + 1;
            float v00 = c[mt][nt][0], v01 = c[mt][nt][1];
            float v10 = c[mt][nt][2], v11 = c[mt][nt][3];
            if (z == 0) {
                float mi0 = mub[gi0], mi1 = mub[gi1];
                float mj0 = mub[gj0], mj1 = mub[gj1];
                v00 -= 1024.f*mi0*mj0; v01 -= 1024.f*mi0*mj1;
                v10 -= 1024.f*mi1*mj0; v11 -= 1024.f*mi1*mj1;
            }
            v00 *= scale; v01 *= scale; v10 *= scale; v11 *= scale;
            *(float2*)&Cb[(size_t)gi0*NN + gj0] = make_float2(v00, v01);
            *(float2*)&Cb[(size_t)gi1*NN + gj0] = make_float2(v10, v11);
            if (bi != bj) {
                Cb[(size_t)gj0*NN + gi0] = v00;
                Cb[(size_t)gj1*NN + gi0] = v01;
                Cb[(size_t)gj0*NN + gi1] = v10;
                Cb[(size_t)gj1*NN + gi1] = v11;
            }
        }
    }
}

// ------- wide-tile tf32 GEMM: CTA 128x256, warp 64x64, 1 CTA/SM -----------
__global__ __launch_bounds__(256,1) void k_mm_w(const float* __restrict__ A, long long sA,
        const float* __restrict__ Bm, long long sB, const float* __restrict__ bias,
        const float* __restrict__ rs,
        float* __restrict__ Cm, long long sC, int K, int relu) {
    extern __shared__ float sm[];
    float* AS = sm;
    float* BS = sm + 3*128*ASTR;
    int bj = blockIdx.x, bi = blockIdx.y, b = blockIdx.z;
    int tid = threadIdx.x;
    int lane = tid & 31, w = tid >> 5;
    int gid = lane >> 2, tg = lane & 3;
    int wm = w & 1, wn = w >> 1;
    int m0w = wm*64, n0w = wn*64;
    const float* Ab = A + (size_t)b*sA + (size_t)(bi*128)*K;
    const float* Bb = Bm + (size_t)b*sB + bj*256;
    int ar = tid >> 1, ak = (tid & 1)*16;
    int bk = tid >> 3, bn = (tid & 7)*32;

    auto loads = [&](int s, int kt) {
        const float* ga = Ab + (size_t)ar*K + kt + ak;
        unsigned da = su32(AS + s*128*ASTR + ar*ASTR + ak);
#pragma unroll
        for (int i = 0; i < 4; ++i) cpa16(da + 16*i, ga + 4*i);
        const float* gb = Bb + (size_t)(kt + bk)*NN + bn;
        unsigned db = su32(BS + s*32*BSTR2 + bk*BSTR2 + bn);
#pragma unroll
        for (int i = 0; i < 8; ++i) cpa16(db + 16*i, gb + 4*i);
        cpcommit();
    };

    float c[4][8][4];
#pragma unroll
    for (int i = 0; i < 4; ++i)
#pragma unroll
        for (int j = 0; j < 8; ++j)
#pragma unroll
            for (int q = 0; q < 4; ++q) c[i][j][q] = 0.f;

    const int NT = K/32;
    loads(0, 0); loads(1, 32);
    for (int it = 0; it < NT; ++it) {
        if (it < NT-1) cpwait<1>(); else cpwait<0>();
        __syncthreads();
        if (it + 2 < NT) loads((it+2)%3, (it+2)*32);
        const float* Asb = AS + (it%3)*128*ASTR;
        const float* Bsb = BS + (it%3)*32*BSTR2;
#pragma unroll
        for (int ks = 0; ks < 4; ++ks) {
            int k0 = ks*8;
            unsigned af[4][4], bf[8][2];
#pragma unroll
            for (int mt = 0; mt < 4; ++mt) {
                int m = m0w + mt*16 + gid;
                af[mt][0] = __float_as_uint(Asb[(m  )*ASTR + k0 + tg]);
                af[mt][1] = __float_as_uint(Asb[(m+8)*ASTR + k0 + tg]);
                af[mt][2] = __float_as_uint(Asb[(m  )*ASTR + k0 + tg + 4]);
                af[mt][3] = __float_as_uint(Asb[(m+8)*ASTR + k0 + tg + 4]);
            }
#pragma unroll
            for (int nt = 0; nt < 8; ++nt) {
                int n = n0w + nt*8 + gid;
                bf[nt][0] = __float_as_uint(Bsb[(k0 + tg    )*BSTR2 + n]);
                bf[nt][1] = __float_as_uint(Bsb[(k0 + tg + 4)*BSTR2 + n]);
            }
#pragma unroll
            for (int mt = 0; mt < 4; ++mt)
#pragma unroll
                for (int nt = 0; nt < 8; ++nt)
                    mma_tf32(c[mt][nt], af[mt][0], af[mt][1], af[mt][2], af[mt][3],
                             bf[nt][0], bf[nt][1]);
        }
    }
    float* Cb = Cm + (size_t)b*sC + (size_t)(bi*128)*NN + bj*256;
#pragma unroll
    for (int mt = 0; mt < 4; ++mt) {
#pragma unroll
        for (int nt = 0; nt < 8; ++nt) {
            int r0 = m0w + mt*16 + gid;
            int cb = n0w + nt*8 + tg*2;
            int gi0 = bi*128 + r0, gi1 = gi0 + 8;
            int gcb = bj*256 + cb;
            float bz0 = bias ? bias[gcb]     : 0.f;
            float bz1 = bias ? bias[gcb + 1] : 0.f;
            float rs0 = rs ? rs[b*NN + gi0] : 1.f;
            float rs1 = rs ? rs[b*NN + gi1] : 1.f;
            float v00 = (c[mt][nt][0] + bz0)*rs0, v01 = (c[mt][nt][1] + bz1)*rs0;
            float v10 = (c[mt][nt][2] + bz0)*rs1, v11 = (c[mt][nt][3] + bz1)*rs1;
            if (relu) {
                v00 = fmaxf(v00, 0.f); v01 = fmaxf(v01, 0.f);
                v10 = fmaxf(v10, 0.f); v11 = fmaxf(v11, 0.f);
            }
            *(float2*)&Cb[(size_t)r0*NN + cb]     = make_float2(v00, v01);
            *(float2*)&Cb[(size_t)(r0+8)*NN + cb] = make_float2(v10, v11);
        }
    }
}

// -------- wide layer-0 GEMM: concat(P,S,C) @ W0g, LN epilogue, ×dinv ------
__global__ __launch_bounds__(256,1) void k_mm3w(const float* __restrict__ P,
        const float* __restrict__ S, const float* __restrict__ C,
        const float* __restrict__ W0g, const float* __restrict__ vw,
        const float* __restrict__ lnmu, const float* __restrict__ lninv,
        const float* __restrict__ dinv, float* __restrict__ Y) {
    extern __shared__ float sm[];
    float* AS = sm;
    float* BS = sm + 3*128*ASTR;
    int bj = blockIdx.x, bi = blockIdx.y, b = blockIdx.z;
    int tid = threadIdx.x;
    int lane = tid & 31, w = tid >> 5;
    int gid = lane >> 2, tg = lane & 3;
    int wm = w & 1, wn = w >> 1;
    int m0w = wm*64, n0w = wn*64;
    size_t arow = (size_t)b*NN*NN + (size_t)(bi*128)*NN;
    const float* Pb = P + arow;
    const float* Sb = S + arow;
    const float* Cc = C + arow;
    int ar = tid >> 1, ak = (tid & 1)*16;
    int bk = tid >> 3, bn = (tid & 7)*32;

    auto loads = [&](int s, int kt) {
        int seg = kt >> 9, ko = kt & 511;
        const float* base = (seg == 0) ? Pb : ((seg == 1) ? Sb : Cc);
        const float* ga = base + (size_t)ar*NN + ko + ak;
        unsigned da = su32(AS + s*128*ASTR + ar*ASTR + ak);
#pragma unroll
        for (int i = 0; i < 4; ++i) cpa16(da + 16*i, ga + 4*i);
        const float* gb = W0g + (size_t)(kt + bk)*DD + bj*256 + bn;
        unsigned db = su32(BS + s*32*BSTR2 + bk*BSTR2 + bn);
#pragma unroll
        for (int i = 0; i < 8; ++i) cpa16(db + 16*i, gb + 4*i);
        cpcommit();
    };

    float c[4][8][4];
#pragma unroll
    for (int i = 0; i < 4; ++i)
#pragma unroll
        for (int j = 0; j < 8; ++j)
#pragma unroll
            for (int q = 0; q < 4; ++q) c[i][j][q] = 0.f;

    const int NT = INDIM/32;
    loads(0, 0); loads(1, 32);
    for (int it = 0; it < NT; ++it) {
        if (it < NT-1) cpwait<1>(); else cpwait<0>();
        __syncthreads();
        if (it + 2 < NT) loads((it+2)%3, (it+2)*32);
        const float* Asb = AS + (it%3)*128*ASTR;
        const float* Bsb = BS + (it%3)*32*BSTR2;
#pragma unroll
        for (int ks = 0; ks < 4; ++ks) {
            int k0 = ks*8;
            unsigned af[4][4], bf[8][2];
#pragma unroll
            for (int mt = 0; mt < 4; ++mt) {
                int m = m0w + mt*16 + gid;
                af[mt][0] = __float_as_uint(Asb[(m  )*ASTR + k0 + tg]);
                af[mt][1] = __float_as_uint(Asb[(m+8)*ASTR + k0 + tg]);
                af[mt][2] = __float_as_uint(Asb[(m  )*ASTR + k0 + tg + 4]);
                af[mt][3] = __float_as_uint(Asb[(m+8)*ASTR + k0 + tg + 4]);
            }
#pragma unroll
            for (int nt = 0; nt < 8; ++nt) {
                int n = n0w + nt*8 + gid;
                bf[nt][0] = __float_as_uint(Bsb[(k0 + tg    )*BSTR2 + n]);
                bf[nt][1] = __float_as_uint(Bsb[(k0 + tg + 4)*BSTR2 + n]);
            }
#pragma unroll
            for (int mt = 0; mt < 4; ++mt)
#pragma unroll
                for (int nt = 0; nt < 8; ++nt)
                    mma_tf32(c[mt][nt], af[mt][0], af[mt][1], af[mt][2], af[mt][3],
                             bf[nt][0], bf[nt][1]);
        }
    }
    float* Cb = Y + (size_t)b*NN*DD + (size_t)(bi*128)*NN + bj*256;
#pragma unroll
    for (int mt = 0; mt < 4; ++mt) {
#pragma unroll
        for (int nt = 0; nt < 8; ++nt) {
            int r0 = m0w + mt*16 + gid;
            int cb = n0w + nt*8 + tg*2;
            int gi0 = bi*128 + r0, gi1 = gi0 + 8;
            int gj0 = bj*256 + cb, gj1 = gj0 + 1;
            float li0 = lninv[b*NN+gi0], lm0 = lnmu[b*NN+gi0]*li0, d0 = dinv[b*NN+gi0];
            float li1 = lninv[b*NN+gi1], lm1 = lnmu[b*NN+gi1]*li1, d1 = dinv[b*NN+gi1];
            float vv0 = vw[gj0], vv1 = vw[gj1];
            float ww0 = vw[DD+gj0], ww1 = vw[DD+gj1];
            float v00 = (c[mt][nt][0]*li0 - lm0*vv0 + ww0)*d0;
            float v01 = (c[mt][nt][1]*li0 - lm0*vv1 + ww1)*d0;
            float v10 = (c[mt][nt][2]*li1 - lm1*vv0 + ww0)*d1;
            float v11 = (c[mt][nt][3]*li1 - lm1*vv1 + ww1)*d1;
            *(float2*)&Cb[(size_t)r0*NN + cb]     = make_float2(v00, v01);
            *(float2*)&Cb[(size_t)(r0+8)*NN + cb] = make_float2(v10, v11);
        }
    }
}

// ---------------- diag std ----------------
__global__ void k_std2(const float* __restrict__ covP, const float* __restrict__ covS,
                       float* __restrict__ sdP, float* __restrict__ sdS) {
    int e = blockIdx.x*blockDim.x + threadIdx.x;
    if (e >= BB*NN) return;
    int b = e >> 9, n = e & 511;
    size_t d = ((size_t)b*NN + n)*NN + n;
    sdP[e] = sqrtf(fmaxf(covP[d], EPSF));
    sdS[e] = sqrtf(fmaxf(covS[d], EPSF));
}

// ------ blocked distributed GJ inverse, Schur 64x64 diag inversion --------
// Per panel: owner publishes its CURRENT rows; ALL CTAs invert the staged
// 64x64 diag block via Schur (2x warp-shfl 32x32 GJ + small GEMM phases);
// each CTA forms G = F@Binv and updates its rows. Panel cols <- -G / Binv.
__global__ __launch_bounds__(256) void k_inv(const float* __restrict__ cov,
                                             float* __restrict__ prec,
                                             float* __restrict__ sdQ) {
    extern __shared__ float smv[];
    float* a_s = smv;                        // 64*IAST
    float* w_s = smv + 64*IAST;              // 64*IWST (Binv, then G)
    float* buf = w_s + 64*IWST;              // 128 (unused; layout keep)
    float* p_s = buf + 128;                  // 2 * 64*IPST
    int cta = blockIdx.x;
    int b = cta >> 3, rb = cta & 7, r0 = rb * 64;
    int tid = threadIdx.x;
    int lane = tid & 31, w = tid >> 5;
    int gid = lane >> 2, tg = lane & 3;
    const float* src = cov + (size_t)b*NN*NN;
    for (int e = tid; e < 64*512; e += 256) {
        int i = e >> 9, j = e & 511;
        float v = src[(size_t)(r0+i)*NN + j];
        if (r0 + i == j) v += 0.001f;
        a_s[i*IAST + j] = v;
    }
    float* stg = g_stage + (size_t)b*NN*NN;
    volatile int* flg = g_flags + b*8;
    __syncthreads();

    for (int p = 0; p < 8; ++p) {
        int c0 = p * 64;
        bool own = (rb == p);
        if (own) {
            // publish current rows (pre-elimination for this panel)
            for (int e = tid; e < 64*512; e += 256) {
                int i = e >> 9, j = e & 511;
                stg[(size_t)(c0+i)*512 + j] = a_s[i*IAST + j];
            }
            __syncthreads();
            __threadfence();
            if (tid == 0) flg[p] = 1;
        } else {
            if (tid == 0) { while (flg[p] == 0) { } }
        }
        __syncthreads();
        // load staged diag block D into w_s (owner reads own copy)
        if (own) {
            for (int e = tid; e < 64*64; e += 256)
                w_s[(e>>6)*IWST + (e&63)] = a_s[(e>>6)*IAST + c0 + (e&63)];
        } else {
            for (int e = tid; e < 64*64; e += 256)
                w_s[(e>>6)*IWST + (e&63)] = __ldcg(&stg[(size_t)(c0+(e>>6))*512 + c0 + (e&63)]);
        }
        __syncthreads();
        // ---- Schur inversion of w_s (64x64) in place ----
        {
            float* T1 = p_s;              // 32*33
            float* T2 = p_s + 32*33;      // 32*33
            int ii = tid >> 3, j0 = (tid & 7) * 4;
            if (tid < 32) inv32_shfl(w_s, IWST);               // A^{-1}
            __syncthreads();
            {   // T1 = Ainv*B ; T2 = C*Ainv
                float acc1[4] = {0,0,0,0}, acc2[4] = {0,0,0,0};
#pragma unroll 8
                for (int k = 0; k < 32; ++k) {
                    float av = w_s[ii*IWST + k];
                    float cv = w_s[(32+ii)*IWST + k];
#pragma unroll
                    for (int q = 0; q < 4; ++q) {
                        acc1[q] += av * w_s[k*IWST + 32 + j0 + q];
                        acc2[q] += cv * w_s[k*IWST + j0 + q];
                    }
                }
#pragma unroll
                for (int q = 0; q < 4; ++q) {
                    T1[ii*33 + j0 + q] = acc1[q];
                    T2[ii*33 + j0 + q] = acc2[q];
                }
            }
            __syncthreads();
            {   // S = D - C*T1 (into D slot)
                float acc[4] = {0,0,0,0};
#pragma unroll 8
                for (int k = 0; k < 32; ++k) {
                    float cv = w_s[(32+ii)*IWST + k];
#pragma unroll
                    for (int q = 0; q < 4; ++q)
                        acc[q] += cv * T1[k*33 + j0 + q];
                }
#pragma unroll
                for (int q = 0; q < 4; ++q)
                    w_s[(32+ii)*IWST + 32 + j0 + q] -= acc[q];
            }
            __syncthreads();
            if (tid < 32) inv32_shfl(w_s + 32*IWST + 32, IWST); // S^{-1}
            __syncthreads();
            {   // X12 = -T1*Sinv -> B slot ; X21 = -Sinv*T2 -> C slot
                float acc1[4] = {0,0,0,0}, acc2[4] = {0,0,0,0};
#pragma unroll 8
                for (int k = 0; k < 32; ++k) {
                    float t1v = T1[ii*33 + k];
                    float siv = w_s[(32+ii)*IWST + 32 + k];
#pragma unroll
                    for (int q = 0; q < 4; ++q) {
                        acc1[q] += t1v * w_s[(32+k)*IWST + 32 + j0 + q];
                        acc2[q] += siv * T2[k*33 + j0 + q];
                    }
                }
#pragma unroll
                for (int q = 0; q < 4; ++q) {
                    w_s[ii*IWST + 32 + j0 + q] = -acc1[q];
                    w_s[(32+ii)*IWST + j0 + q] = -acc2[q];
                }
            }
            __syncthreads();
            {   // X11 = Ainv - X12*T2 -> A slot
                float acc[4] = {0,0,0,0};
#pragma unroll 8
                for (int k = 0; k < 32; ++k) {
                    float xv = w_s[ii*IWST + 32 + k];
#pragma unroll
                    for (int q = 0; q < 4; ++q)
                        acc[q] += xv * T2[k*33 + j0 + q];
                }
#pragma unroll
                for (int q = 0; q < 4; ++q)
                    w_s[ii*IWST + j0 + q] -= acc[q];
            }
            __syncthreads();
        }
        if (!own) {
            // G = F @ Binv  (F = a_s panel block), result -> p_s0, then w_s
            int n = w*8 + gid;
            float acc[4][4];
#pragma unroll
            for (int i = 0; i < 4; ++i)
#pragma unroll
                for (int q = 0; q < 4; ++q) acc[i][q] = 0.f;
#pragma unroll 2
            for (int ks = 0; ks < 8; ++ks) {
                int k0 = ks*8;
                unsigned ahi[4][4], alo[4][4];
#pragma unroll
                for (int mt = 0; mt < 4; ++mt) {
                    int m = mt*16 + gid;
                    tfsplit(a_s[m*IAST + c0 + k0 + tg],        ahi[mt][0], alo[mt][0]);
                    tfsplit(a_s[(m+8)*IAST + c0 + k0 + tg],    ahi[mt][1], alo[mt][1]);
                    tfsplit(a_s[m*IAST + c0 + k0 + tg + 4],    ahi[mt][2], alo[mt][2]);
                    tfsplit(a_s[(m+8)*IAST + c0 + k0 + tg + 4],ahi[mt][3], alo[mt][3]);
                }
                unsigned bhi[2], blo[2];
                tfsplit(w_s[(k0+tg  )*IWST + n], bhi[0], blo[0]);
                tfsplit(w_s[(k0+tg+4)*IWST + n], bhi[1], blo[1]);
#pragma unroll
                for (int mt = 0; mt < 4; ++mt) {
                    mma_tf32(acc[mt], ahi[mt][0],ahi[mt][1],ahi[mt][2],ahi[mt][3], bhi[0],bhi[1]);
                    mma_tf32(acc[mt], ahi[mt][0],ahi[mt][1],ahi[mt][2],ahi[mt][3], blo[0],blo[1]);
                    mma_tf32(acc[mt], alo[mt][0],alo[mt][1],alo[mt][2],alo[mt][3], bhi[0],bhi[1]);
                }
            }
#pragma unroll
            for (int mt = 0; mt < 4; ++mt) {
                int r = mt*16 + gid;
                int cpos = w*8 + tg*2;
                *(float2*)&p_s[r*IPST + cpos]     = make_float2(acc[mt][0], acc[mt][1]);
                *(float2*)&p_s[(r+8)*IPST + cpos] = make_float2(acc[mt][2], acc[mt][3]);
            }
            __syncthreads();
            // w_s <- G
            for (int e = tid; e < 64*64; e += 256)
                w_s[(e>>6)*IWST + (e&63)] = p_s[(e>>6)*IPST + (e&63)];
            __syncthreads();
        }
        // ---- update rows from stage: owner A = Binv@O ; else A -= G@O ----
        {
            // prefetch chunk 0
#pragma unroll
            for (int i = 0; i < 8; ++i) {
                int idx = tid + i*256;
                int row = idx >> 5, j4 = idx & 31;
                cpa16(su32(p_s + row*IPST + j4*4),
                      stg + (size_t)(c0+row)*512 + j4*4);
            }
            cpcommit();
        }
        for (int ch = 0; ch < 4; ++ch) {
            cpwait<0>();
            __syncthreads();
            if (ch + 1 < 4) {
                float* dst = p_s + ((ch+1)&1)*(64*IPST);
#pragma unroll
                for (int i = 0; i < 8; ++i) {
                    int idx = tid + i*256;
                    int row = idx >> 5, j4 = idx & 31;
                    cpa16(su32(dst + row*IPST + j4*4),
                          stg + (size_t)(c0+row)*512 + (ch+1)*128 + j4*4);
                }
                cpcommit();
            }
            const float* pb = p_s + (ch&1)*(64*IPST);
            float acc[4][2][4];
#pragma unroll
            for (int i = 0; i < 4; ++i)
#pragma unroll
                for (int j = 0; j < 2; ++j)
#pragma unroll
                    for (int q = 0; q < 4; ++q) acc[i][j][q] = 0.f;
#pragma unroll 2
            for (int ks = 0; ks < 8; ++ks) {
                int k0 = ks*8;
                unsigned ahi[4][4], alo[4][4];
#pragma unroll
                for (int mt = 0; mt < 4; ++mt) {
                    int m = mt*16 + gid;
                    tfsplit(w_s[m*IWST + k0 + tg],        ahi[mt][0], alo[mt][0]);
                    tfsplit(w_s[(m+8)*IWST + k0 + tg],    ahi[mt][1], alo[mt][1]);
                    tfsplit(w_s[m*IWST + k0 + tg + 4],    ahi[mt][2], alo[mt][2]);
                    tfsplit(w_s[(m+8)*IWST + k0 + tg + 4],ahi[mt][3], alo[mt][3]);
                }
                unsigned bhi[2][2], blo[2][2];
#pragma unroll
                for (int nt = 0; nt < 2; ++nt) {
                    int n = w*16 + nt*8 + gid;
                    tfsplit(pb[(k0+tg  )*IPST + n], bhi[nt][0], blo[nt][0]);
                    tfsplit(pb[(k0+tg+4)*IPST + n], bhi[nt][1], blo[nt][1]);
                }
#pragma unroll
                for (int mt = 0; mt < 4; ++mt)
#pragma unroll
                    for (int nt = 0; nt < 2; ++nt) {
                        mma_tf32(acc[mt][nt], ahi[mt][0],ahi[mt][1],ahi[mt][2],ahi[mt][3], bhi[nt][0],bhi[nt][1]);
                        mma_tf32(acc[mt][nt], ahi[mt][0],ahi[mt][1],ahi[mt][2],ahi[mt][3], blo[nt][0],blo[nt][1]);
                        mma_tf32(acc[mt][nt], alo[mt][0],alo[mt][1],alo[mt][2],alo[mt][3], bhi[nt][0],bhi[nt][1]);
                    }
            }
#pragma unroll
            for (int mt = 0; mt < 4; ++mt)
#pragma unroll
                for (int nt = 0; nt < 2; ++nt) {
                    int r = mt*16 + gid;
                    int cpos = ch*128 + w*16 + nt*8 + tg*2;
                    if (own) {
                        *(float2*)&a_s[r*IAST + cpos] = make_float2(acc[mt][nt][0], acc[mt][nt][1]);
                        *(float2*)&a_s[(r+8)*IAST + cpos] = make_float2(acc[mt][nt][2], acc[mt][nt][3]);
                    } else {
                        float2* A0 = (float2*)&a_s[r*IAST + cpos];
                        float2 v = *A0;
                        v.x -= acc[mt][nt][0]; v.y -= acc[mt][nt][1];
                        *A0 = v;
                        float2* A1 = (float2*)&a_s[(r+8)*IAST + cpos];
                        v = *A1;
                        v.x -= acc[mt][nt][2]; v.y -= acc[mt][nt][3];
                        *A1 = v;
                    }
                }
        }
        __syncthreads();
        // panel-col overwrite: owner <- Binv ; non-owner <- -G
        for (int e = tid; e < 64*64; e += 256) {
            int i = e >> 6, j = e & 63;
            float v = w_s[i*IWST + j];
            a_s[i*IAST + c0 + j] = own ? v : -v;
        }
        __syncthreads();
    }
    float* dst = prec + (size_t)b*NN*NN;
    for (int e = tid; e < 64*512; e += 256) {
        int i = e >> 9, j = e & 511;
        float v = a_s[i*IAST + j];
        dst[(size_t)(r0 + i)*NN + j] = v;
        if (r0 + i == j) sdQ[b*NN + j] = sqrtf(fmaxf(v, EPSF));
    }
}

// ------- fused corr + partial-corr + pairwise dots -------
__global__ void k_pcdots(const float* __restrict__ covP, const float* __restrict__ sdP,
                         const float* __restrict__ covS, const float* __restrict__ sdS,
                         const float* __restrict__ prec, const float* __restrict__ sdQ,
                         float* __restrict__ P, float* __restrict__ S,
                         float* __restrict__ C, float* __restrict__ parts) {
    __shared__ float red[256];
    float t1 = tanhf(1.f);
    int b = blockIdx.y, ch = blockIdx.x;
    size_t base = (size_t)b*NN*NN + (size_t)ch*8192;
    float a[6] = {0,0,0,0,0,0};
    for (int e0 = threadIdx.x; e0 < 8192; e0 += 256) {
        size_t e = base + e0;
        int r = ch*8192 + e0; int i = r >> 9, j = r & 511;
        float vp, vs, c;
        if (i == j) { vp = 1.f; vs = 1.f; c = t1; }
        else {
            vp = covP[e] / (sdP[b*NN+i]*sdP[b*NN+j]);
            if (!isfinite(vp)) vp = 0.f;
            vs = covS[e] / (sdS[b*NN+i]*sdS[b*NN+j]);
            if (!isfinite(vs)) vs = 0.f;
            c = tanhf(-prec[e] / (sdQ[b*NN+i]*sdQ[b*NN+j]));
        }
        P[e] = vp; S[e] = vs; C[e] = c;
        a[0] += vp*vp; a[1] += vs*vs; a[2] += c*c;
        a[3] += vp*vs; a[4] += vp*c; a[5] += vs*c;
    }
    for (int v = 0; v < 6; ++v) {
        red[threadIdx.x] = a[v]; __syncthreads();
        for (int o = 128; o > 0; o >>= 1) {
            if (threadIdx.x < o) red[threadIdx.x] += red[threadIdx.x + o];
            __syncthreads();
        }
        if (threadIdx.x == 0) parts[((size_t)b*32 + ch)*6 + v] = red[0];
        __syncthreads();
    }
}

// ---------------- sims + softmax alphas ----------------
__global__ void k_sims(const float* __restrict__ parts, const float* __restrict__ gamma,
                       float* __restrict__ alph) {
    int b = threadIdx.x;
    if (b >= BB) return;
    float F[6] = {0,0,0,0,0,0};
    for (int ch = 0; ch < 32; ++ch)
        for (int v = 0; v < 6; ++v) F[v] += parts[((size_t)b*32 + ch)*6 + v];
    float dC = tanhf(1.f);
    float dv[3] = {1.f, 1.f, dC};
    float D[3][3];
    D[0][0] = (F[0] - NN*dv[0]*dv[0]) * 0.5f;
    D[1][1] = (F[1] - NN*dv[1]*dv[1]) * 0.5f;
    D[2][2] = (F[2] - NN*dv[2]*dv[2]) * 0.5f;
    D[0][1] = D[1][0] = (F[3] - NN*dv[0]*dv[1]) * 0.5f;
    D[0][2] = D[2][0] = (F[4] - NN*dv[0]*dv[2]) * 0.5f;
    D[1][2] = D[2][1] = (F[5] - NN*dv[1]*dv[2]) * 0.5f;
    float rowsum[3], tot2 = 0.f;
    for (int v = 0; v < 3; ++v) {
        rowsum[v] = D[v][0] + D[v][1] + D[v][2];
        tot2 += rowsum[v];
    }
    float sims[3];
    for (int v = 0; v < 3; ++v) {
        float num = 0.5f * (rowsum[v] - D[v][v]);
        float nv = sqrtf(fmaxf(D[v][v], 0.f));
        float oo = 0.25f * (tot2 - 2.f*rowsum[v] + D[v][v]);
        float no = sqrtf(fmaxf(oo, 0.f));
        float den = fmaxf(nv, EPSF) * fmaxf(no, EPSF);
        sims[v] = num / den;
    }
    float g = gamma[0];
    float m = fmaxf(g*sims[0], fmaxf(g*sims[1], g*sims[2]));
    float e0 = expf(g*sims[0]-m), e1 = expf(g*sims[1]-m), e2 = expf(g*sims[2]-m);
    float si = 1.f / (e0 + e1 + e2);
    alph[b*4+0] = e0*si; alph[b*4+1] = e1*si; alph[b*4+2] = e2*si;
}

// ------- fuse + rowsum + LN row stats -------
__global__ __launch_bounds__(128) void k_fuse_rs(const float* __restrict__ P,
                      const float* __restrict__ S, const float* __restrict__ C,
                      const float* __restrict__ alph, float* __restrict__ Af,
                      float* __restrict__ dinv, float* __restrict__ lnmu,
                      float* __restrict__ lninv) {
    __shared__ float red[128];
    int bn = blockIdx.x;
    int b = bn >> 9, i = bn & 511;
    float aP = alph[b*4+0], aS = alph[b*4+1], aC = alph[b*4+2];
    size_t base = (size_t)bn*NN;
    float s = 0.f, s1 = 0.f, s2 = 0.f;
    for (int j = threadIdx.x; j < NN; j += 128) {
        float p = P[base+j], sv = S[base+j], cv = C[base+j];
        float v = aP*p + aS*sv + aC*cv;
        if (j == i) v = 1.f;
        Af[base+j] = v;
        s += v;
        s1 += p + sv + cv;
        s2 += p*p + sv*sv + cv*cv;
    }
    red[threadIdx.x] = s; __syncthreads();
    for (int o = 64; o > 0; o >>= 1) {
        if (threadIdx.x < o) red[threadIdx.x] += red[threadIdx.x + o];
        __syncthreads();
    }
    if (threadIdx.x == 0) dinv[bn] = rsqrtf(fmaxf(red[0], EPSF));
    __syncthreads();
    red[threadIdx.x] = s1; __syncthreads();
    for (int o = 64; o > 0; o >>= 1) {
        if (threadIdx.x < o) red[threadIdx.x] += red[threadIdx.x + o];
        __syncthreads();
    }
    float mu = red[0] * (1.f/INDIM);
    __syncthreads();
    red[threadIdx.x] = s2; __syncthreads();
    for (int o = 64; o > 0; o >>= 1) {
        if (threadIdx.x < o) red[threadIdx.x] += red[threadIdx.x + o];
        __syncthreads();
    }
    if (threadIdx.x == 0) {
        lnmu[bn] = mu;
        lninv[bn] = rsqrtf(red[0]*(1.f/INDIM) - mu*mu + 1e-5f);
    }
}

// ---------------- head ----------------
__global__ void k_head1(const float* __restrict__ H, float* __restrict__ part) {
    int b = blockIdx.y, ch = blockIdx.x, d = threadIdx.x;
    float s = 0.f;
#pragma unroll 8
    for (int r = 0; r < 32; ++r)
        s += H[((size_t)b*NN + ch*32 + r)*DD + d];
    part[((size_t)b*16 + ch)*DD + d] = s;
}

__global__ void k_head2(const float* __restrict__ part, const float* __restrict__ Wc,
                        const float* __restrict__ bc, float* __restrict__ out) {
    __shared__ float red[512];
    int b = blockIdx.x, d = threadIdx.x;
    float s = 0.f;
    for (int ch = 0; ch < 16; ++ch) s += part[((size_t)b*16 + ch)*DD + d];
    red[d] = (s * (1.f/NN)) * Wc[d];
    __syncthreads();
    for (int o = 256; o > 0; o >>= 1) {
        if (d < o) red[d] += red[d + o];
        __syncthreads();
    }
    if (d == 0) out[b] = 1.f / (1.f + expf(-(red[0] + bc[0])));
}

// ---------------- host ----------------
extern "C" void kernel_launch(void* const* d_in, const int* in_sizes, int n_in,
                              void* d_out, int out_size) {
    const float* x    = (const float*)d_in[0];
    const float* gam  = (const float*)d_in[1];
    const float* lng  = (const float*)d_in[2];
    const float* lnb  = (const float*)d_in[3];
    const float* W0   = (const float*)d_in[4];
    const float* b0   = (const float*)d_in[5];
    const float* W1   = (const float*)d_in[6];
    const float* b1   = (const float*)d_in[7];
    const float* W2   = (const float*)d_in[8];
    const float* b2   = (const float*)d_in[9];
    const float* Wc   = (const float*)d_in[10];
    const float* bc   = (const float*)d_in[11];
    float* out = (float*)d_out;

    float *pXt,*pRc,*pMu,*pCovP,*pCovS,*pP,*pS,*pPrec,*pC,*pAf,*pY,*pH;
    float *pSdP,*pSdS,*pSdQ,*pParts,*pAl,*pDinv,*pStage,*pLnmu,*pLninv,*pW0g,*pVw,*pVwp;
    cudaGetSymbolAddress((void**)&pXt,   g_xt);
    cudaGetSymbolAddress((void**)&pRc,   g_rc);
    cudaGetSymbolAddress((void**)&pMu,   g_mu);
    cudaGetSymbolAddress((void**)&pCovP, g_covP);
    cudaGetSymbolAddress((void**)&pCovS, g_covS);
    cudaGetSymbolAddress((void**)&pP,    g_P);
    cudaGetSymbolAddress((void**)&pS,    g_S);
    cudaGetSymbolAddress((void**)&pPrec, g_prec);
    cudaGetSymbolAddress((void**)&pC,    g_C);
    cudaGetSymbolAddress((void**)&pAf,   g_Af);
    cudaGetSymbolAddress((void**)&pY,    g_Ybuf);
    cudaGetSymbolAddress((void**)&pH,    g_Hbuf);
    cudaGetSymbolAddress((void**)&pSdP,  g_sdP);
    cudaGetSymbolAddress((void**)&pSdS,  g_sdS);
    cudaGetSymbolAddress((void**)&pSdQ,  g_sdQ);
    cudaGetSymbolAddress((void**)&pParts,g_parts);
    cudaGetSymbolAddress((void**)&pAl,   g_alph);
    cudaGetSymbolAddress((void**)&pDinv, g_dinv);
    cudaGetSymbolAddress((void**)&pStage,g_stage);
    cudaGetSymbolAddress((void**)&pLnmu, g_lnmu);
    cudaGetSymbolAddress((void**)&pLninv,g_lninv);
    cudaGetSymbolAddress((void**)&pW0g,  g_W0g);
    cudaGetSymbolAddress((void**)&pVw,   g_vw);
    cudaGetSymbolAddress((void**)&pVwp,  g_vwp);

    const int INV_SMEM  = (64*IAST + 64*IWST + 128 + 2*64*IPST) * 4;
    const int GRAM_SMEM = (6*128*ASTR) * 4;
    const int MMW_SMEM  = (3*128*ASTR + 3*32*BSTR2) * 4;
    cudaFuncSetAttribute(k_inv,    cudaFuncAttributeMaxDynamicSharedMemorySize, INV_SMEM);
    cudaFuncSetAttribute(k_gram_t, cudaFuncAttributeMaxDynamicSharedMemorySize, GRAM_SMEM);
    cudaFuncSetAttribute(k_mm_w,   cudaFuncAttributeMaxDynamicSharedMemorySize, MMW_SMEM);
    cudaFuncSetAttribute(k_mm3w,   cudaFuncAttributeMaxDynamicSharedMemorySize, MMW_SMEM);

    const float GSCALE = (float)(1.0 / (1023.0 + 1e-8));

    // launch idx 3 = k_inv -> profiled by ncu (verify Schur diag inversion)
    k_transpose<<<dim3(NN/32, TT/32, BB), dim3(32,8)>>>(x, pXt);          // 0
    k_sort<<<BB*NN, 512>>>(pXt, pRc, pMu);                                 // 1
    k_gram_t<<<dim3(10, BB, 2), 256, GRAM_SMEM>>>(pXt, pRc, pMu,
                                                  pCovP, pCovS, GSCALE);   // 2
    k_inv<<<128, 256, INV_SMEM>>>(pCovP, pPrec, pSdQ);                     // 3
    k_std2<<<(BB*NN+255)/256, 256>>>(pCovP, pCovS, pSdP, pSdS);            // 4
    k_prepw0<<<512, 256>>>(W0, lng, pW0g);                                 // 5
    k_prepvw<<<96, 512>>>(W0, lng, lnb, pVwp);                             // 6
    k_vwred<<<1, 512>>>(pVwp, b0, pVw);                                    // 7

    k_pcdots<<<dim3(32, BB), 256>>>(pCovP, pSdP, pCovS, pSdS, pPrec, pSdQ,
                                    pP, pS, pC, pParts);
    k_sims<<<1, 32>>>(pParts, gam, pAl);
    k_fuse_rs<<<BB*NN, 128>>>(pP, pS, pC, pAl, pAf, pDinv, pLnmu, pLninv);

    long long sM = (long long)NN*DD, sA2 = (long long)NN*NN;
    k_mm3w<<<dim3(2,4,BB), 256, MMW_SMEM>>>(pP, pS, pC, pW0g, pVw, pLnmu, pLninv, pDinv, pY);
    k_mm_w<<<dim3(2,4,BB), 256, MMW_SMEM>>>(pAf, sA2, pY, sM, (const float*)0, pDinv, pH, sM, DD, 1);
    k_mm_w<<<dim3(2,4,BB), 256, MMW_SMEM>>>(pH,  sM,  W1, 0LL, b1, pDinv, pY, sM, DD, 0);
    k_mm_w<<<dim3(2,4,BB), 256, MMW_SMEM>>>(pAf, sA2, pY, sM, (const float*)0, pDinv, pH, sM, DD, 1);
    k_mm_w<<<dim3(2,4,BB), 256, MMW_SMEM>>>(pH,  sM,  W2, 0LL, b2, pDinv, pY, sM, DD, 0);
    k_mm_w<<<dim3(2,4,BB), 256, MMW_SMEM>>>(pAf, sA2, pY, sM, (const float*)0, pDinv, pH, sM, DD, 1);

    k_head1<<<dim3(16, BB), 512>>>(pH, pStage);
    k_head2<<<BB, 512>>>(pStage, Wc, bc, out);

    (void)in_sizes; (void)n_in; (void)out_size;
}